// round 11
// baseline (speedup 1.0000x reference)
#include <cuda_runtime.h>
#include <math.h>

#define BB 16
#define PP 500
#define NN 501
#define EE 128
#define HH 8
#define HD 16
#define LL 3
#define LEAKY 0.2f
#define LN_EPS 1e-5f
#define IT 16
#define JT 16
#define NT 32    // ceil(NN/JT)
#define MW 16    // mask words per row (501 bits -> 16 u32)
#define PROW 132 // padded p row: 8*16 + 4
#define NQ (NN * HH)          // 4008
// dynamic smem layout (floats)
#define OFF_QS   0
#define OFF_SS   NQ                   // 4008
#define OFF_XS   (2 * NQ)             // 8016, two buffers of 2048
#define OFF_P    (2 * NQ + 2 * JT * EE)  // 12112, two buffers of 2112
#define DYN_FLOATS (OFF_P + 2 * JT * PROW)   // 16336
#define DYN_BYTES (DYN_FLOATS * 4)           // 65344

// Scratch (device globals; no runtime allocation)
__device__ float g_x[2][(size_t)BB * NN * EE];
__device__ float g_xW[(size_t)BB * NN * EE];
__device__ float g_ei[BB * NN * HH];
__device__ float g_ej[BB * NN * HH];
__device__ float g_gmax[BB * HH];
__device__ unsigned int g_adjbits[BB * NN * MW];
__device__ int g_mask_kind;

// FFMA-only exp, rel err ~2e-7, no MUFU.
__device__ __forceinline__ float fast_exp(float x) {
    x = fmaxf(x, -80.f);
    float y = x * 1.4426950408889634f;
    float t = y + 12582912.f;
    int n = __float_as_int(t) - 0x4B400000;
    float f = y - (t - 12582912.f);
    float u = f * 0.6931471805599453f;
    float r = fmaf(u, 1.38888889e-3f, 8.33333333e-3f);
    r = fmaf(r, u, 4.16666667e-2f);
    r = fmaf(r, u, 1.66666667e-1f);
    r = fmaf(r, u, 0.5f);
    r = fmaf(r, u, 1.0f);
    r = fmaf(r, u, 1.0f);
    return r * __int_as_float((n + 127) << 23);
}
__device__ __forceinline__ float fsel_ge(float a, float b, float thr) {
    return (a >= thr) ? a : b;
}

// ---------------------------------------------------------------------------
__global__ void probe_mask_kernel(const unsigned int* __restrict__ w) {
    __shared__ int s_u8, s_f32;
    if (threadIdx.x == 0) { s_u8 = 0; s_f32 = 0; }
    __syncthreads();
    for (int idx = threadIdx.x; idx < 4096; idx += blockDim.x) {
        unsigned int v = w[idx];
        if (v == 0x3f800000u) atomicOr(&s_f32, 1);
        else if (v > 1u)      atomicOr(&s_u8, 1);
    }
    __syncthreads();
    if (threadIdx.x == 0) g_mask_kind = s_f32 ? 2 : (s_u8 ? 1 : 0);
}

__global__ void convert_bits_kernel(const void* __restrict__ adj_raw) {
    int bn = blockIdx.x;
    int t = threadIdx.x;
    int kind = g_mask_kind;
    bool v = false;
    if (t < NN) {
        size_t idx = (size_t)bn * NN + t;
        if (kind == 1)      v = ((const unsigned char*)adj_raw)[idx] != 0;
        else if (kind == 2) v = ((const float*)adj_raw)[idx] != 0.0f;
        else                v = ((const int*)adj_raw)[idx] != 0;
    }
    unsigned int word = __ballot_sync(0xffffffffu, v);
    if ((t & 31) == 0) g_adjbits[bn * MW + (t >> 5)] = word;
}

// ---------------------------------------------------------------------------
__global__ void embed_kernel(const float* __restrict__ depot_xy,
                             const float* __restrict__ node5,
                             const float* __restrict__ depW,
                             const float* __restrict__ depb,
                             const float* __restrict__ nodeW,
                             const float* __restrict__ nodeb) {
    int bn = blockIdx.x;
    int b = bn / NN, n = bn % NN;
    int e = threadIdx.x;
    float v;
    if (n == 0) {
        float x0 = depot_xy[b * 2 + 0];
        float x1 = depot_xy[b * 2 + 1];
        v = fmaf(x0, depW[0 * EE + e], fmaf(x1, depW[1 * EE + e], depb[e]));
    } else {
        int p = n - 1;
        const float* f = node5 + ((size_t)b * PP + p) * 5;
        v = nodeb[e];
        #pragma unroll
        for (int k = 0; k < 5; k++) v = fmaf(f[k], nodeW[k * EE + e], v);
    }
    g_x[0][(size_t)bn * EE + e] = v;
}

// ---------------------------------------------------------------------------
// xW = x @ W[l] + fused ei/ej. grid = 501, block = 256, 16 rows/block.
// ---------------------------------------------------------------------------
__global__ void __launch_bounds__(256) xw_kernel(int src,
                                                const float* __restrict__ Wl,
                                                const float* __restrict__ attn_l) {
    int t = threadIdx.x;
    int e = t & 127, half = t >> 7;
    int row0 = blockIdx.x * 16;
    __shared__ float xs[16][EE];
    const float* x = &g_x[src][0];
    {
        const float4* s4 = (const float4*)(x + (size_t)row0 * EE);
        float4* d4 = (float4*)&xs[0][0];
        for (int idx = t; idx < 16 * EE / 4; idx += 256) d4[idx] = s4[idx];
    }
    __syncthreads();

    float acc[8];
    #pragma unroll
    for (int r = 0; r < 8; r++) acc[r] = 0.f;

    for (int k = 0; k < EE; k += 4) {
        float w0 = Wl[(k + 0) * EE + e];
        float w1 = Wl[(k + 1) * EE + e];
        float w2 = Wl[(k + 2) * EE + e];
        float w3 = Wl[(k + 3) * EE + e];
        #pragma unroll
        for (int r = 0; r < 8; r++) {
            float4 xv = *(const float4*)&xs[half * 8 + r][k];
            acc[r] = fmaf(xv.x, w0, acc[r]);
            acc[r] = fmaf(xv.y, w1, acc[r]);
            acc[r] = fmaf(xv.z, w2, acc[r]);
            acc[r] = fmaf(xv.w, w3, acc[r]);
        }
    }

    int h = e >> 4, d = e & 15;
    float a1 = attn_l[h * 2 * HD + d];
    float a2 = attn_l[h * 2 * HD + HD + d];
    #pragma unroll
    for (int r = 0; r < 8; r++) {
        int row = row0 + half * 8 + r;
        g_xW[(size_t)row * EE + e] = acc[r];
        float vi = acc[r] * a1, vj = acc[r] * a2;
        #pragma unroll
        for (int off = 8; off; off >>= 1) {
            vi += __shfl_down_sync(0xffffffffu, vi, off, 16);
            vj += __shfl_down_sync(0xffffffffu, vj, off, 16);
        }
        if (d == 0) { g_ei[row * HH + h] = vi; g_ej[row * HH + h] = vj; }
    }
}

// ---------------------------------------------------------------------------
// Per-batch, per-head global max of ej. grid = BB, block = 256.
// ---------------------------------------------------------------------------
__global__ void gmax_kernel() {
    int b = blockIdx.x;
    int t = threadIdx.x;
    __shared__ float part[32][HH];
    int g = t >> 3, h = t & 7;
    const float* ejb = g_ej + (size_t)b * NN * HH;
    float mx = -INFINITY;
    for (int j = g; j < NN; j += 32) mx = fmaxf(mx, ejb[j * HH + h]);
    part[g][h] = mx;
    __syncthreads();
    if (t < HH) {
        float m = part[0][t];
        #pragma unroll
        for (int g2 = 1; g2 < 32; g2++) m = fmaxf(m, part[g2][t]);
        g_gmax[b * HH + t] = m;
    }
}

// ---------------------------------------------------------------------------
// Attention + residual + LayerNorm + ELU. grid = (32, B), block = 256.
// Factorized softmax with per-block Q/S tables (dynamic smem) and a
// double-buffered single-sync-per-tile pipeline (LDG overlapped w/ compute).
// ---------------------------------------------------------------------------
__global__ void __launch_bounds__(256) attn_kernel(const float* __restrict__ gamma,
                                                   const float* __restrict__ beta,
                                                   int dst, float* __restrict__ dout) {
    int b = blockIdx.y;
    int i0 = blockIdx.x * IT;
    int t = threadIdx.x;

    extern __shared__ float dyn[];
    float* Qs = dyn + OFF_QS;
    float* Ss = dyn + OFF_SS;
    // xs buffer k: dyn + OFF_XS + k*JT*EE ; p buffer k: dyn + OFF_P + k*JT*PROW

    __shared__ float Pi_s[IT * HH], Ri_s[IT * HH], Ti_s[IT * HH];
    __shared__ unsigned int mask_s[IT][MW];
    __shared__ float s_s[IT * HH];
    __shared__ float lnred[8][4][2];

    const float* xWb = g_xW + (size_t)b * NN * EE;
    const float* ejb = g_ej + (size_t)b * NN * HH;

    // mask bits
    {
        int ii = t >> 4, w = t & 15;
        int i = i0 + ii;
        mask_s[ii][w] = (i < NN) ? g_adjbits[(b * NN + i) * MW + w] : 0u;
    }
    // per-i factors
    if (t < IT * HH) {
        int i = i0 + (t >> 3);
        float ei = (i < NN) ? g_ei[(b * NN + i) * HH + (t & 7)] : 0.f;
        float w = ei + g_gmax[b * HH + (t & 7)];
        float m = fmaxf(w, LEAKY * w);
        Pi_s[t] = fast_exp(ei - m);
        Ri_s[t] = fast_exp(0.2f * ei - m);
        Ti_s[t] = fast_exp(-m);
    }
    // Q/S tables for all j
    for (int idx = t; idx < NQ; idx += 256) {
        float e = ejb[idx];
        Qs[idx] = fast_exp(e);
        Ss[idx] = fast_exp(0.2f * e);
    }
    __syncthreads();

    // thread roles
    int c = t & 63;          // float2 column: cols 2c, 2c+1
    int grp = t >> 6;        // rows grp*4 .. grp*4+3
    int h = c >> 3;
    bool sowner = ((c & 7) == 0);
    int ii_t = t >> 4;       // p-compute: row
    int jj_t = t & 15;       // p-compute: tile col

    float Pi_r[HH], Ri_r[HH], Ti_r[HH];
    #pragma unroll
    for (int hh = 0; hh < HH; hh++) {
        Pi_r[hh] = Pi_s[ii_t * HH + hh];
        Ri_r[hh] = Ri_s[ii_t * HH + hh];
        Ti_r[hh] = Ti_s[ii_t * HH + hh];
    }

    const float4* xW4 = (const float4*)xWb;

    // helper lambdas (macros in spirit)
    #define STAGE_TILE(J0, XSBUF, PBUF)                                           \
    {                                                                             \
        /* xs */                                                                  \
        float4* d4 = (float4*)(XSBUF);                                            \
        int idx0 = t, idx1 = t + 256;                                             \
        int ja = (J0) + (idx0 >> 5), jb2 = (J0) + (idx1 >> 5);                    \
        d4[idx0] = (ja < NN) ? xW4[(size_t)ja * 32 + (idx0 & 31)]                 \
                             : make_float4(0.f, 0.f, 0.f, 0.f);                   \
        d4[idx1] = (jb2 < NN) ? xW4[(size_t)jb2 * 32 + (idx1 & 31)]               \
                              : make_float4(0.f, 0.f, 0.f, 0.f);                  \
        /* p */                                                                   \
        int j = (J0) + jj_t;                                                      \
        float* pd = (PBUF) + jj_t * PROW + ii_t;                                  \
        if (j < NN && ((mask_s[ii_t][j >> 5] >> (j & 31)) & 1u)) {                \
            float4 q0 = *(const float4*)&Qs[j * 8];                               \
            float4 q1 = *(const float4*)&Qs[j * 8 + 4];                           \
            float4 sp0 = *(const float4*)&Ss[j * 8];                              \
            float4 sp1 = *(const float4*)&Ss[j * 8 + 4];                          \
            pd[0 * 16] = fsel_ge(Pi_r[0] * q0.x, Ri_r[0] * sp0.x, Ti_r[0]);       \
            pd[1 * 16] = fsel_ge(Pi_r[1] * q0.y, Ri_r[1] * sp0.y, Ti_r[1]);       \
            pd[2 * 16] = fsel_ge(Pi_r[2] * q0.z, Ri_r[2] * sp0.z, Ti_r[2]);       \
            pd[3 * 16] = fsel_ge(Pi_r[3] * q0.w, Ri_r[3] * sp0.w, Ti_r[3]);       \
            pd[4 * 16] = fsel_ge(Pi_r[4] * q1.x, Ri_r[4] * sp1.x, Ti_r[4]);       \
            pd[5 * 16] = fsel_ge(Pi_r[5] * q1.y, Ri_r[5] * sp1.y, Ti_r[5]);       \
            pd[6 * 16] = fsel_ge(Pi_r[6] * q1.z, Ri_r[6] * sp1.z, Ti_r[6]);       \
            pd[7 * 16] = fsel_ge(Pi_r[7] * q1.w, Ri_r[7] * sp1.w, Ti_r[7]);       \
        } else {                                                                  \
            _Pragma("unroll")                                                     \
            for (int hh = 0; hh < HH; hh++) pd[hh * 16] = 0.f;                    \
        }                                                                         \
    }

    float2 acc[4];
    float sacc[4];
    #pragma unroll
    for (int r = 0; r < 4; r++) { acc[r] = make_float2(0.f, 0.f); sacc[r] = 0.f; }

    // prologue: stage tile 0 into buffer 0
    STAGE_TILE(0, dyn + OFF_XS, dyn + OFF_P);
    __syncthreads();

    int cur = 0;
    for (int tile = 0; tile < NT; tile++) {
        float* xs = dyn + OFF_XS + cur * (JT * EE);
        float* ps = dyn + OFF_P + cur * (JT * PROW);
        int nxt = cur ^ 1;
        float* xsn = dyn + OFF_XS + nxt * (JT * EE);
        float* psn = dyn + OFF_P + nxt * (JT * PROW);
        bool havenext = (tile + 1) < NT;
        int j0n = (tile + 1) * JT;

        // issue next-tile xW loads into registers (latency overlapped)
        float4 r0 = make_float4(0.f, 0.f, 0.f, 0.f);
        float4 r1 = make_float4(0.f, 0.f, 0.f, 0.f);
        if (havenext) {
            int idx0 = t, idx1 = t + 256;
            int ja = j0n + (idx0 >> 5), jb2 = j0n + (idx1 >> 5);
            if (ja < NN) r0 = xW4[(size_t)ja * 32 + (idx0 & 31)];
            if (jb2 < NN) r1 = xW4[(size_t)jb2 * 32 + (idx1 & 31)];
        }

        // compute on current buffers
        #pragma unroll 4
        for (int jj = 0; jj < JT; jj++) {
            float4 p4 = *(const float4*)&ps[jj * PROW + h * 16 + grp * 4];
            float2 xv = *(const float2*)&xs[jj * EE + 2 * c];
            acc[0].x = fmaf(p4.x, xv.x, acc[0].x);
            acc[0].y = fmaf(p4.x, xv.y, acc[0].y);
            acc[1].x = fmaf(p4.y, xv.x, acc[1].x);
            acc[1].y = fmaf(p4.y, xv.y, acc[1].y);
            acc[2].x = fmaf(p4.z, xv.x, acc[2].x);
            acc[2].y = fmaf(p4.z, xv.y, acc[2].y);
            acc[3].x = fmaf(p4.w, xv.x, acc[3].x);
            acc[3].y = fmaf(p4.w, xv.y, acc[3].y);
            if (sowner) {
                sacc[0] += p4.x; sacc[1] += p4.y;
                sacc[2] += p4.z; sacc[3] += p4.w;
            }
        }

        // publish next tile
        if (havenext) {
            ((float4*)xsn)[t] = r0;
            ((float4*)xsn)[t + 256] = r1;
            int j = j0n + jj_t;
            float* pd = psn + jj_t * PROW + ii_t;
            if (j < NN && ((mask_s[ii_t][j >> 5] >> (j & 31)) & 1u)) {
                float4 q0 = *(const float4*)&Qs[j * 8];
                float4 q1 = *(const float4*)&Qs[j * 8 + 4];
                float4 sp0 = *(const float4*)&Ss[j * 8];
                float4 sp1 = *(const float4*)&Ss[j * 8 + 4];
                pd[0 * 16] = fsel_ge(Pi_r[0] * q0.x, Ri_r[0] * sp0.x, Ti_r[0]);
                pd[1 * 16] = fsel_ge(Pi_r[1] * q0.y, Ri_r[1] * sp0.y, Ti_r[1]);
                pd[2 * 16] = fsel_ge(Pi_r[2] * q0.z, Ri_r[2] * sp0.z, Ti_r[2]);
                pd[3 * 16] = fsel_ge(Pi_r[3] * q0.w, Ri_r[3] * sp0.w, Ti_r[3]);
                pd[4 * 16] = fsel_ge(Pi_r[4] * q1.x, Ri_r[4] * sp1.x, Ti_r[4]);
                pd[5 * 16] = fsel_ge(Pi_r[5] * q1.y, Ri_r[5] * sp1.y, Ti_r[5]);
                pd[6 * 16] = fsel_ge(Pi_r[6] * q1.z, Ri_r[6] * sp1.z, Ti_r[6]);
                pd[7 * 16] = fsel_ge(Pi_r[7] * q1.w, Ri_r[7] * sp1.w, Ti_r[7]);
            } else {
                #pragma unroll
                for (int hh = 0; hh < HH; hh++) pd[hh * 16] = 0.f;
            }
        }
        __syncthreads();
        cur = nxt;
    }

    if (sowner) {
        #pragma unroll
        for (int r = 0; r < 4; r++) s_s[(grp * 4 + r) * HH + h] = sacc[r];
    }
    __syncthreads();

    // epilogue: normalize, residual, LayerNorm, ELU
    float2 val[4];
    float s1[4], s2[4];
    #pragma unroll
    for (int r = 0; r < 4; r++) {
        int ii = grp * 4 + r;
        int i = i0 + ii;
        float sv = s_s[ii * HH + h];
        float2 xwv = (i < NN) ? *(const float2*)(xWb + (size_t)i * EE + 2 * c)
                              : make_float2(0.f, 0.f);
        float inv = 1.f / sv;
        val[r].x = acc[r].x * inv + xwv.x;
        val[r].y = acc[r].y * inv + xwv.y;
        s1[r] = val[r].x + val[r].y;
        s2[r] = val[r].x * val[r].x + val[r].y * val[r].y;
    }
    #pragma unroll
    for (int off = 16; off; off >>= 1) {
        #pragma unroll
        for (int r = 0; r < 4; r++) {
            s1[r] += __shfl_xor_sync(0xffffffffu, s1[r], off);
            s2[r] += __shfl_xor_sync(0xffffffffu, s2[r], off);
        }
    }
    int warp = t >> 5;
    if ((t & 31) == 0) {
        #pragma unroll
        for (int r = 0; r < 4; r++) { lnred[warp][r][0] = s1[r]; lnred[warp][r][1] = s2[r]; }
    }
    __syncthreads();

    float* o = (dst < 0) ? dout : &g_x[dst][0];
    int w0 = grp * 2;
    float gx = gamma[2 * c], gy = gamma[2 * c + 1];
    float bx = beta[2 * c],  by = beta[2 * c + 1];
    #pragma unroll
    for (int r = 0; r < 4; r++) {
        int ii = grp * 4 + r;
        int i = i0 + ii;
        if (i >= NN) continue;
        float a = lnred[w0][r][0] + lnred[w0 + 1][r][0];
        float q = lnred[w0][r][1] + lnred[w0 + 1][r][1];
        float mu = a * (1.f / EE);
        float var = q * (1.f / EE) - mu * mu;
        float rstd = rsqrtf(var + LN_EPS);
        float yx = (val[r].x - mu) * rstd * gx + bx;
        float yy = (val[r].y - mu) * rstd * gy + by;
        yx = yx > 0.f ? yx : (fast_exp(yx) - 1.f);
        yy = yy > 0.f ? yy : (fast_exp(yy) - 1.f);
        *(float2*)(o + ((size_t)(b * NN + i)) * EE + 2 * c) = make_float2(yx, yy);
    }
}

// ---------------------------------------------------------------------------
extern "C" void kernel_launch(void* const* d_in, const int* in_sizes, int n_in,
                              void* d_out, int out_size) {
    const float* depot_xy = (const float*)d_in[0];
    const float* node5    = (const float*)d_in[1];
    const void*  adj_raw  = (const void*)d_in[2];
    const float* depW  = (const float*)d_in[3];
    const float* depb  = (const float*)d_in[4];
    const float* nodeW = (const float*)d_in[5];
    const float* nodeb = (const float*)d_in[6];
    const float* W     = (const float*)d_in[7];
    const float* attn  = (const float*)d_in[8];
    const float* ln_g  = (const float*)d_in[9];
    const float* ln_b  = (const float*)d_in[10];
    float* out = (float*)d_out;

    cudaFuncSetAttribute(attn_kernel,
                         cudaFuncAttributeMaxDynamicSharedMemorySize, DYN_BYTES);

    probe_mask_kernel<<<1, 256>>>((const unsigned int*)adj_raw);
    convert_bits_kernel<<<BB * NN, 512>>>(adj_raw);

    embed_kernel<<<BB * NN, EE>>>(depot_xy, node5, depW, depb, nodeW, nodeb);

    dim3 agrid((NN + IT - 1) / IT, BB);
    int cur = 0;
    for (int l = 0; l < LL; l++) {
        xw_kernel<<<BB * NN / 16, 256>>>(cur,
                                         W + (size_t)l * EE * EE,
                                         attn + (size_t)l * HH * 2 * HD);
        gmax_kernel<<<BB, 256>>>();
        int dst = (l == LL - 1) ? -1 : (1 - cur);
        attn_kernel<<<agrid, 256, DYN_BYTES>>>(ln_g + (size_t)l * EE,
                                               ln_b + (size_t)l * EE,
                                               dst, out);
        cur = 1 - cur;
    }
}

// round 12
// speedup vs baseline: 1.2649x; 1.2649x over previous
#include <cuda_runtime.h>
#include <math.h>

#define BB 16
#define PP 500
#define NN 501
#define EE 128
#define HH 8
#define HD 16
#define LL 3
#define LEAKY 0.2f
#define LN_EPS 1e-5f
#define IT 32
#define JT 16
#define NT 32    // ceil(NN/JT)
#define MW 16    // mask words per row (501 bits -> 16 u32)
#define PH 36    // p head stride (floats)
#define PJ 292   // p jj stride (floats) = 8*36+4

// Scratch (device globals; no runtime allocation)
__device__ float g_x[2][(size_t)BB * NN * EE];
__device__ float g_xW[(size_t)BB * NN * EE];
__device__ float g_ei[BB * NN * HH];
__device__ float g_ej[BB * NN * HH];
__device__ unsigned int g_adjbits[BB * NN * MW];
__device__ int g_mask_kind;

// FFMA-only exp, rel err ~2e-7, no MUFU.
__device__ __forceinline__ float fast_exp(float x) {
    x = fmaxf(x, -80.f);
    float y = x * 1.4426950408889634f;
    float t = y + 12582912.f;
    int n = __float_as_int(t) - 0x4B400000;
    float f = y - (t - 12582912.f);
    float u = f * 0.6931471805599453f;
    float r = fmaf(u, 1.38888889e-3f, 8.33333333e-3f);
    r = fmaf(r, u, 4.16666667e-2f);
    r = fmaf(r, u, 1.66666667e-1f);
    r = fmaf(r, u, 0.5f);
    r = fmaf(r, u, 1.0f);
    r = fmaf(r, u, 1.0f);
    return r * __int_as_float((n + 127) << 23);
}
__device__ __forceinline__ float fsel_ge(float a, float b, float thr) {
    return (a >= thr) ? a : b;
}

// ---------------------------------------------------------------------------
__global__ void probe_mask_kernel(const unsigned int* __restrict__ w) {
    __shared__ int s_u8, s_f32;
    if (threadIdx.x == 0) { s_u8 = 0; s_f32 = 0; }
    __syncthreads();
    for (int idx = threadIdx.x; idx < 4096; idx += blockDim.x) {
        unsigned int v = w[idx];
        if (v == 0x3f800000u) atomicOr(&s_f32, 1);
        else if (v > 1u)      atomicOr(&s_u8, 1);
    }
    __syncthreads();
    if (threadIdx.x == 0) g_mask_kind = s_f32 ? 2 : (s_u8 ? 1 : 0);
}

__global__ void convert_bits_kernel(const void* __restrict__ adj_raw) {
    int bn = blockIdx.x;
    int t = threadIdx.x;
    int kind = g_mask_kind;
    bool v = false;
    if (t < NN) {
        size_t idx = (size_t)bn * NN + t;
        if (kind == 1)      v = ((const unsigned char*)adj_raw)[idx] != 0;
        else if (kind == 2) v = ((const float*)adj_raw)[idx] != 0.0f;
        else                v = ((const int*)adj_raw)[idx] != 0;
    }
    unsigned int word = __ballot_sync(0xffffffffu, v);
    if ((t & 31) == 0) g_adjbits[bn * MW + (t >> 5)] = word;
}

// ---------------------------------------------------------------------------
__global__ void embed_kernel(const float* __restrict__ depot_xy,
                             const float* __restrict__ node5,
                             const float* __restrict__ depW,
                             const float* __restrict__ depb,
                             const float* __restrict__ nodeW,
                             const float* __restrict__ nodeb) {
    int bn = blockIdx.x;
    int b = bn / NN, n = bn % NN;
    int e = threadIdx.x;
    float v;
    if (n == 0) {
        float x0 = depot_xy[b * 2 + 0];
        float x1 = depot_xy[b * 2 + 1];
        v = fmaf(x0, depW[0 * EE + e], fmaf(x1, depW[1 * EE + e], depb[e]));
    } else {
        int p = n - 1;
        const float* f = node5 + ((size_t)b * PP + p) * 5;
        v = nodeb[e];
        #pragma unroll
        for (int k = 0; k < 5; k++) v = fmaf(f[k], nodeW[k * EE + e], v);
    }
    g_x[0][(size_t)bn * EE + e] = v;
}

// ---------------------------------------------------------------------------
// xW = x @ W[l] + fused ei/ej. grid = 501, block = 256, 16 rows/block.
// ---------------------------------------------------------------------------
__global__ void __launch_bounds__(256) xw_kernel(int src,
                                                const float* __restrict__ Wl,
                                                const float* __restrict__ attn_l) {
    int t = threadIdx.x;
    int e = t & 127, half = t >> 7;
    int row0 = blockIdx.x * 16;
    __shared__ float xs[16][EE];
    const float* x = &g_x[src][0];
    {
        const float4* s4 = (const float4*)(x + (size_t)row0 * EE);
        float4* d4 = (float4*)&xs[0][0];
        for (int idx = t; idx < 16 * EE / 4; idx += 256) d4[idx] = s4[idx];
    }
    __syncthreads();

    float acc[8];
    #pragma unroll
    for (int r = 0; r < 8; r++) acc[r] = 0.f;

    for (int k = 0; k < EE; k += 4) {
        float w0 = Wl[(k + 0) * EE + e];
        float w1 = Wl[(k + 1) * EE + e];
        float w2 = Wl[(k + 2) * EE + e];
        float w3 = Wl[(k + 3) * EE + e];
        #pragma unroll
        for (int r = 0; r < 8; r++) {
            float4 xv = *(const float4*)&xs[half * 8 + r][k];
            acc[r] = fmaf(xv.x, w0, acc[r]);
            acc[r] = fmaf(xv.y, w1, acc[r]);
            acc[r] = fmaf(xv.z, w2, acc[r]);
            acc[r] = fmaf(xv.w, w3, acc[r]);
        }
    }

    int h = e >> 4, d = e & 15;
    float a1 = attn_l[h * 2 * HD + d];
    float a2 = attn_l[h * 2 * HD + HD + d];
    #pragma unroll
    for (int r = 0; r < 8; r++) {
        int row = row0 + half * 8 + r;
        g_xW[(size_t)row * EE + e] = acc[r];
        float vi = acc[r] * a1, vj = acc[r] * a2;
        #pragma unroll
        for (int off = 8; off; off >>= 1) {
            vi += __shfl_down_sync(0xffffffffu, vi, off, 16);
            vj += __shfl_down_sync(0xffffffffu, vj, off, 16);
        }
        if (d == 0) { g_ei[row * HH + h] = vi; g_ej[row * HH + h] = vj; }
    }
}

// ---------------------------------------------------------------------------
// Attention + residual + LayerNorm + ELU. grid = (16, B), block = 256.
// IT=32 rows/block. Warp w == head w. Lane l: rg = l&7 (rows rg*4..rg*4+3),
// q = l>>3, col group cg = w*4+q (cols 4cg..4cg+3). 4x4 register tile.
// Factorized softmax (R7): p = Pi*Qj or Ri*Sj selected by threshold Ti.
// ---------------------------------------------------------------------------
__global__ void __launch_bounds__(256) attn_kernel(const float* __restrict__ gamma,
                                                   const float* __restrict__ beta,
                                                   int dst, float* __restrict__ dout) {
    int b = blockIdx.y;
    int i0 = blockIdx.x * IT;
    int t = threadIdx.x;

    __shared__ float Pi_s[IT * HH], Ri_s[IT * HH], Ti_s[IT * HH];  // 3 KB
    __shared__ float gpart[32][HH];                                 // 1 KB
    __shared__ float gmax[HH];
    __shared__ unsigned int mask_s[IT][MW];                         // 2 KB
    __shared__ __align__(16) float xs[JT][EE];                      // 8 KB
    __shared__ __align__(16) float p_s[JT * PJ];                    // 18.7 KB
    __shared__ float Qt[JT][HH], St[JT][HH];                        // 1 KB
    __shared__ float s_s[IT * HH];                                  // 1 KB
    __shared__ float lnred[8][8][4][2];                             // 2 KB
    __shared__ float mu_s[IT], rstd_s[IT];

    const float* xWb = g_xW + (size_t)b * NN * EE;
    const float* ejb = g_ej + (size_t)b * NN * HH;

    // global per-head max of ej
    {
        int g = t >> 3, hh = t & 7;
        float mx = -INFINITY;
        for (int j = g; j < NN; j += 32) mx = fmaxf(mx, ejb[j * HH + hh]);
        gpart[g][hh] = mx;
    }
    // mask bits: 512 words
    {
        #pragma unroll
        for (int k = 0; k < 2; k++) {
            int idx = t + 256 * k;
            int ii = idx >> 4, w2 = idx & 15;
            int i = i0 + ii;
            mask_s[ii][w2] = (i < NN) ? g_adjbits[(b * NN + i) * MW + w2] : 0u;
        }
    }
    __syncthreads();
    if (t < HH) {
        float mx = gpart[0][t];
        #pragma unroll
        for (int g = 1; g < 32; g++) mx = fmaxf(mx, gpart[g][t]);
        gmax[t] = mx;
    }
    __syncthreads();
    // per-i factors: t -> (ii = t>>3, hh = t&7); exactly 256
    {
        int i = i0 + (t >> 3);
        float ei = (i < NN) ? g_ei[(b * NN + i) * HH + (t & 7)] : 0.f;
        float w = ei + gmax[t & 7];
        float m = fmaxf(w, LEAKY * w);
        Pi_s[t] = fast_exp(ei - m);
        Ri_s[t] = fast_exp(0.2f * ei - m);
        Ti_s[t] = fast_exp(-m);
    }
    __syncthreads();

    // thread roles
    int w = t >> 5;          // warp == head
    int l = t & 31;
    int rg = l & 7;          // row group: rows rg*4..rg*4+3
    int q = l >> 3;          // quad
    int cg = w * 4 + q;      // col group: cols 4cg..4cg+3
    bool sowner = (q == 0);
    int ii_t = t >> 3;       // p-compute row
    int jj_t = t & 7;        // p-compute: jj_t and jj_t+8

    float Pi_r[HH], Ri_r[HH], Ti_r[HH];
    #pragma unroll
    for (int hh = 0; hh < HH; hh++) {
        Pi_r[hh] = Pi_s[ii_t * HH + hh];
        Ri_r[hh] = Ri_s[ii_t * HH + hh];
        Ti_r[hh] = Ti_s[ii_t * HH + hh];
    }

    float4 acc[4];
    float sacc[4];
    #pragma unroll
    for (int r = 0; r < 4; r++) { acc[r] = make_float4(0.f, 0.f, 0.f, 0.f); sacc[r] = 0.f; }

    for (int j0 = 0; j0 < NN; j0 += JT) {
        // stage xW j-tile
        {
            float4* d4 = (float4*)&xs[0][0];
            #pragma unroll
            for (int k = 0; k < 2; k++) {
                int idx = t + 256 * k;
                int jj = idx >> 5;
                int j = j0 + jj;
                d4[idx] = (j < NN) ? ((const float4*)(xWb + (size_t)j * EE))[idx & 31]
                                   : make_float4(0.f, 0.f, 0.f, 0.f);
            }
        }
        // per-tile Qj/Sj factors
        if (t < JT * HH) {
            int jj = t >> 3, hh = t & 7;
            int j = j0 + jj;
            float e = (j < NN) ? ejb[j * HH + hh] : 0.f;
            Qt[jj][hh] = fast_exp(e);
            St[jj][hh] = fast_exp(0.2f * e);
        }
        __syncthreads();

        // p-compute: thread (ii_t, jj_t) and (ii_t, jj_t+8), all 8 heads
        #pragma unroll
        for (int k = 0; k < 2; k++) {
            int jj = jj_t + 8 * k;
            int j = j0 + jj;
            float* pd = &p_s[jj * PJ + ii_t];
            if (j < NN && ((mask_s[ii_t][j >> 5] >> (j & 31)) & 1u)) {
                float4 q0 = *(const float4*)&Qt[jj][0];
                float4 q1 = *(const float4*)&Qt[jj][4];
                float4 sp0 = *(const float4*)&St[jj][0];
                float4 sp1 = *(const float4*)&St[jj][4];
                pd[0 * PH] = fsel_ge(Pi_r[0] * q0.x, Ri_r[0] * sp0.x, Ti_r[0]);
                pd[1 * PH] = fsel_ge(Pi_r[1] * q0.y, Ri_r[1] * sp0.y, Ti_r[1]);
                pd[2 * PH] = fsel_ge(Pi_r[2] * q0.z, Ri_r[2] * sp0.z, Ti_r[2]);
                pd[3 * PH] = fsel_ge(Pi_r[3] * q0.w, Ri_r[3] * sp0.w, Ti_r[3]);
                pd[4 * PH] = fsel_ge(Pi_r[4] * q1.x, Ri_r[4] * sp1.x, Ti_r[4]);
                pd[5 * PH] = fsel_ge(Pi_r[5] * q1.y, Ri_r[5] * sp1.y, Ti_r[5]);
                pd[6 * PH] = fsel_ge(Pi_r[6] * q1.z, Ri_r[6] * sp1.z, Ti_r[6]);
                pd[7 * PH] = fsel_ge(Pi_r[7] * q1.w, Ri_r[7] * sp1.w, Ti_r[7]);
            } else {
                #pragma unroll
                for (int hh = 0; hh < HH; hh++) pd[hh * PH] = 0.f;
            }
        }
        __syncthreads();

        // inner: per jj: LDS.128 p4 (rows) + LDS.128 xv4 (cols) + 16 FFMA
        #pragma unroll 4
        for (int jj = 0; jj < JT; jj++) {
            float4 p4 = *(const float4*)&p_s[jj * PJ + w * PH + rg * 4];
            float4 xv = *(const float4*)&xs[jj][4 * cg];
            acc[0].x = fmaf(p4.x, xv.x, acc[0].x);
            acc[0].y = fmaf(p4.x, xv.y, acc[0].y);
            acc[0].z = fmaf(p4.x, xv.z, acc[0].z);
            acc[0].w = fmaf(p4.x, xv.w, acc[0].w);
            acc[1].x = fmaf(p4.y, xv.x, acc[1].x);
            acc[1].y = fmaf(p4.y, xv.y, acc[1].y);
            acc[1].z = fmaf(p4.y, xv.z, acc[1].z);
            acc[1].w = fmaf(p4.y, xv.w, acc[1].w);
            acc[2].x = fmaf(p4.z, xv.x, acc[2].x);
            acc[2].y = fmaf(p4.z, xv.y, acc[2].y);
            acc[2].z = fmaf(p4.z, xv.z, acc[2].z);
            acc[2].w = fmaf(p4.z, xv.w, acc[2].w);
            acc[3].x = fmaf(p4.w, xv.x, acc[3].x);
            acc[3].y = fmaf(p4.w, xv.y, acc[3].y);
            acc[3].z = fmaf(p4.w, xv.z, acc[3].z);
            acc[3].w = fmaf(p4.w, xv.w, acc[3].w);
            if (sowner) {
                sacc[0] += p4.x; sacc[1] += p4.y;
                sacc[2] += p4.z; sacc[3] += p4.w;
            }
        }
        __syncthreads();
    }

    if (sowner) {
        #pragma unroll
        for (int r = 0; r < 4; r++) s_s[(rg * 4 + r) * HH + w] = sacc[r];
    }
    __syncthreads();

    // epilogue: normalize + residual, then two-stage LayerNorm
    float4 val[4];
    #pragma unroll
    for (int r = 0; r < 4; r++) {
        int ii = rg * 4 + r;
        int i = i0 + ii;
        float sv = s_s[ii * HH + w];
        float4 xwv = (i < NN) ? *(const float4*)(xWb + (size_t)i * EE + 4 * cg)
                              : make_float4(0.f, 0.f, 0.f, 0.f);
        float inv = 1.f / sv;
        val[r].x = acc[r].x * inv + xwv.x;
        val[r].y = acc[r].y * inv + xwv.y;
        val[r].z = acc[r].z * inv + xwv.z;
        val[r].w = acc[r].w * inv + xwv.w;
        float s1 = val[r].x + val[r].y + val[r].z + val[r].w;
        float s2 = val[r].x * val[r].x + val[r].y * val[r].y +
                   val[r].z * val[r].z + val[r].w * val[r].w;
        // reduce over the 4 lanes sharing rg (xor 8, 16)
        s1 += __shfl_xor_sync(0xffffffffu, s1, 8);
        s2 += __shfl_xor_sync(0xffffffffu, s2, 8);
        s1 += __shfl_xor_sync(0xffffffffu, s1, 16);
        s2 += __shfl_xor_sync(0xffffffffu, s2, 16);
        if (sowner) { lnred[w][rg][r][0] = s1; lnred[w][rg][r][1] = s2; }
    }
    __syncthreads();
    if (t < IT) {          // one thread per row: sum across 8 warps
        int rg2 = t >> 2, r2 = t & 3;
        float a = 0.f, qq = 0.f;
        #pragma unroll
        for (int w2 = 0; w2 < 8; w2++) {
            a += lnred[w2][rg2][r2][0];
            qq += lnred[w2][rg2][r2][1];
        }
        float mu = a * (1.f / EE);
        float var = qq * (1.f / EE) - mu * mu;
        mu_s[t] = mu;
        rstd_s[t] = rsqrtf(var + LN_EPS);
    }
    __syncthreads();

    float* o = (dst < 0) ? dout : &g_x[dst][0];
    float4 gv = *(const float4*)&gamma[4 * cg];
    float4 bv = *(const float4*)&beta[4 * cg];
    #pragma unroll
    for (int r = 0; r < 4; r++) {
        int ii = rg * 4 + r;
        int i = i0 + ii;
        if (i >= NN) continue;
        float mu = mu_s[ii], rstd = rstd_s[ii];
        float y0 = (val[r].x - mu) * rstd * gv.x + bv.x;
        float y1 = (val[r].y - mu) * rstd * gv.y + bv.y;
        float y2 = (val[r].z - mu) * rstd * gv.z + bv.z;
        float y3 = (val[r].w - mu) * rstd * gv.w + bv.w;
        y0 = y0 > 0.f ? y0 : (fast_exp(y0) - 1.f);
        y1 = y1 > 0.f ? y1 : (fast_exp(y1) - 1.f);
        y2 = y2 > 0.f ? y2 : (fast_exp(y2) - 1.f);
        y3 = y3 > 0.f ? y3 : (fast_exp(y3) - 1.f);
        *(float4*)(o + ((size_t)(b * NN + i)) * EE + 4 * cg) =
            make_float4(y0, y1, y2, y3);
    }
}

// ---------------------------------------------------------------------------
extern "C" void kernel_launch(void* const* d_in, const int* in_sizes, int n_in,
                              void* d_out, int out_size) {
    const float* depot_xy = (const float*)d_in[0];
    const float* node5    = (const float*)d_in[1];
    const void*  adj_raw  = (const void*)d_in[2];
    const float* depW  = (const float*)d_in[3];
    const float* depb  = (const float*)d_in[4];
    const float* nodeW = (const float*)d_in[5];
    const float* nodeb = (const float*)d_in[6];
    const float* W     = (const float*)d_in[7];
    const float* attn  = (const float*)d_in[8];
    const float* ln_g  = (const float*)d_in[9];
    const float* ln_b  = (const float*)d_in[10];
    float* out = (float*)d_out;

    probe_mask_kernel<<<1, 256>>>((const unsigned int*)adj_raw);
    convert_bits_kernel<<<BB * NN, 512>>>(adj_raw);

    embed_kernel<<<BB * NN, EE>>>(depot_xy, node5, depW, depb, nodeW, nodeb);

    dim3 agrid((NN + IT - 1) / IT, BB);
    int cur = 0;
    for (int l = 0; l < LL; l++) {
        xw_kernel<<<BB * NN / 16, 256>>>(cur,
                                         W + (size_t)l * EE * EE,
                                         attn + (size_t)l * HH * 2 * HD);
        int dst = (l == LL - 1) ? -1 : (1 - cur);
        attn_kernel<<<agrid, 256>>>(ln_g + (size_t)l * EE,
                                    ln_b + (size_t)l * EE,
                                    dst, out);
        cur = 1 - cur;
    }
}

// round 14
// speedup vs baseline: 1.3462x; 1.0643x over previous
#include <cuda_runtime.h>
#include <math.h>

#define BB 16
#define PP 500
#define NN 501
#define EE 128
#define HH 8
#define HD 16
#define LL 3
#define LEAKY 0.2f
#define LN_EPS 1e-5f
#define IT 32
#define JT 16
#define NT 32    // ceil(NN/JT)
#define MW 16    // mask words per row (501 bits -> 16 u32)
#define PH 36    // p head stride (floats)
#define PJ 292   // p jj stride (floats) = 8*36+4
#define NROWS (BB * NN)          // 8016
#define XWROWS 32                // rows per xw block
#define XWGRID ((NROWS + XWROWS - 1) / XWROWS)   // 251
#define XW_SMEM ((EE * EE + XWROWS * EE) * 4)    // 80 KB

// Scratch (device globals; no runtime allocation)
__device__ float g_x[2][(size_t)BB * NN * EE];
__device__ float g_xW[(size_t)BB * NN * EE];
__device__ float g_ei[BB * NN * HH];
__device__ float g_ej[BB * NN * HH];
__device__ unsigned int g_adjbits[BB * NN * MW];
__device__ int g_mask_kind;

// FFMA-only exp, rel err ~2e-7, no MUFU.
__device__ __forceinline__ float fast_exp(float x) {
    x = fmaxf(x, -80.f);
    float y = x * 1.4426950408889634f;
    float t = y + 12582912.f;
    int n = __float_as_int(t) - 0x4B400000;
    float f = y - (t - 12582912.f);
    float u = f * 0.6931471805599453f;
    float r = fmaf(u, 1.38888889e-3f, 8.33333333e-3f);
    r = fmaf(r, u, 4.16666667e-2f);
    r = fmaf(r, u, 1.66666667e-1f);
    r = fmaf(r, u, 0.5f);
    r = fmaf(r, u, 1.0f);
    r = fmaf(r, u, 1.0f);
    return r * __int_as_float((n + 127) << 23);
}
__device__ __forceinline__ float fsel_ge(float a, float b, float thr) {
    return (a >= thr) ? a : b;
}

// ---------------------------------------------------------------------------
__global__ void probe_mask_kernel(const unsigned int* __restrict__ w) {
    __shared__ int s_u8, s_f32;
    if (threadIdx.x == 0) { s_u8 = 0; s_f32 = 0; }
    __syncthreads();
    for (int idx = threadIdx.x; idx < 4096; idx += blockDim.x) {
        unsigned int v = w[idx];
        if (v == 0x3f800000u) atomicOr(&s_f32, 1);
        else if (v > 1u)      atomicOr(&s_u8, 1);
    }
    __syncthreads();
    if (threadIdx.x == 0) g_mask_kind = s_f32 ? 2 : (s_u8 ? 1 : 0);
}

__global__ void convert_bits_kernel(const void* __restrict__ adj_raw) {
    int bn = blockIdx.x;
    int t = threadIdx.x;
    int kind = g_mask_kind;
    bool v = false;
    if (t < NN) {
        size_t idx = (size_t)bn * NN + t;
        if (kind == 1)      v = ((const unsigned char*)adj_raw)[idx] != 0;
        else if (kind == 2) v = ((const float*)adj_raw)[idx] != 0.0f;
        else                v = ((const int*)adj_raw)[idx] != 0;
    }
    unsigned int word = __ballot_sync(0xffffffffu, v);
    if ((t & 31) == 0) g_adjbits[bn * MW + (t >> 5)] = word;
}

// ---------------------------------------------------------------------------
__global__ void embed_kernel(const float* __restrict__ depot_xy,
                             const float* __restrict__ node5,
                             const float* __restrict__ depW,
                             const float* __restrict__ depb,
                             const float* __restrict__ nodeW,
                             const float* __restrict__ nodeb) {
    int bn = blockIdx.x;
    int b = bn / NN, n = bn % NN;
    int e = threadIdx.x;
    float v;
    if (n == 0) {
        float x0 = depot_xy[b * 2 + 0];
        float x1 = depot_xy[b * 2 + 1];
        v = fmaf(x0, depW[0 * EE + e], fmaf(x1, depW[1 * EE + e], depb[e]));
    } else {
        int p = n - 1;
        const float* f = node5 + ((size_t)b * PP + p) * 5;
        v = nodeb[e];
        #pragma unroll
        for (int k = 0; k < 5; k++) v = fmaf(f[k], nodeW[k * EE + e], v);
    }
    g_x[0][(size_t)bn * EE + e] = v;
}

// ---------------------------------------------------------------------------
// xW = x @ W[l] + fused ei/ej. grid = 251, block = 256, 32 rows/block.
// W (64 KB) + x rows (16 KB) staged in dynamic smem; thread = 4 cols x 4 rows.
// ---------------------------------------------------------------------------
__global__ void __launch_bounds__(256) xw_kernel(int src,
                                                const float* __restrict__ Wl,
                                                const float* __restrict__ attn_l) {
    extern __shared__ float sm[];
    float* ws = sm;                 // [k][e], 128*128
    float* xs = sm + EE * EE;       // [r][k], 32*128
    int t = threadIdx.x;
    int row0 = blockIdx.x * XWROWS;

    // stage W (4096 float4) and x rows (1024 float4)
    {
        const float4* W4 = (const float4*)Wl;
        float4* ws4 = (float4*)ws;
        #pragma unroll
        for (int k = 0; k < 16; k++) ws4[t + 256 * k] = W4[t + 256 * k];
        const float4* x4 = (const float4*)(&g_x[src][0] + (size_t)row0 * EE);
        float4* xs4 = (float4*)xs;
        int maxf4 = (NROWS - row0) * (EE / 4);
        #pragma unroll
        for (int k = 0; k < 4; k++) {
            int idx = t + 256 * k;
            xs4[idx] = (idx < maxf4) ? x4[idx] : make_float4(0.f, 0.f, 0.f, 0.f);
        }
    }
    __syncthreads();

    int c4 = t & 31;     // cols 4*c4 .. 4*c4+3
    int rg = t >> 5;     // local rows 4*rg .. 4*rg+3

    float4 acc[4];
    #pragma unroll
    for (int r = 0; r < 4; r++) acc[r] = make_float4(0.f, 0.f, 0.f, 0.f);

    #pragma unroll 8
    for (int k = 0; k < EE; k += 4) {
        float4 w0 = *(const float4*)&ws[(k + 0) * EE + 4 * c4];
        float4 w1 = *(const float4*)&ws[(k + 1) * EE + 4 * c4];
        float4 w2 = *(const float4*)&ws[(k + 2) * EE + 4 * c4];
        float4 w3 = *(const float4*)&ws[(k + 3) * EE + 4 * c4];
        #pragma unroll
        for (int r = 0; r < 4; r++) {
            float4 xv = *(const float4*)&xs[(rg * 4 + r) * EE + k];  // broadcast
            acc[r].x = fmaf(xv.x, w0.x, acc[r].x);
            acc[r].y = fmaf(xv.x, w0.y, acc[r].y);
            acc[r].z = fmaf(xv.x, w0.z, acc[r].z);
            acc[r].w = fmaf(xv.x, w0.w, acc[r].w);
            acc[r].x = fmaf(xv.y, w1.x, acc[r].x);
            acc[r].y = fmaf(xv.y, w1.y, acc[r].y);
            acc[r].z = fmaf(xv.y, w1.z, acc[r].z);
            acc[r].w = fmaf(xv.y, w1.w, acc[r].w);
            acc[r].x = fmaf(xv.z, w2.x, acc[r].x);
            acc[r].y = fmaf(xv.z, w2.y, acc[r].y);
            acc[r].z = fmaf(xv.z, w2.z, acc[r].z);
            acc[r].w = fmaf(xv.z, w2.w, acc[r].w);
            acc[r].x = fmaf(xv.w, w3.x, acc[r].x);
            acc[r].y = fmaf(xv.w, w3.y, acc[r].y);
            acc[r].z = fmaf(xv.w, w3.z, acc[r].z);
            acc[r].w = fmaf(xv.w, w3.w, acc[r].w);
        }
    }

    // epilogue: store xW + fused ei/ej head reductions
    int h = c4 >> 2;
    int dq = (c4 & 3) * 4;
    float4 a1 = *(const float4*)&attn_l[h * 2 * HD + dq];
    float4 a2 = *(const float4*)&attn_l[h * 2 * HD + HD + dq];
    #pragma unroll
    for (int r = 0; r < 4; r++) {
        int row = row0 + rg * 4 + r;
        if (row >= NROWS) break;
        *(float4*)(g_xW + (size_t)row * EE + 4 * c4) = acc[r];
        float vi = acc[r].x * a1.x + acc[r].y * a1.y + acc[r].z * a1.z + acc[r].w * a1.w;
        float vj = acc[r].x * a2.x + acc[r].y * a2.y + acc[r].z * a2.z + acc[r].w * a2.w;
        vi += __shfl_xor_sync(0xffffffffu, vi, 1);
        vj += __shfl_xor_sync(0xffffffffu, vj, 1);
        vi += __shfl_xor_sync(0xffffffffu, vi, 2);
        vj += __shfl_xor_sync(0xffffffffu, vj, 2);
        if ((c4 & 3) == 0) {
            g_ei[row * HH + h] = vi;
            g_ej[row * HH + h] = vj;
        }
    }
}

// ---------------------------------------------------------------------------
// Attention + residual + LayerNorm + ELU. grid = (16, B), block = 256.
// IT=32 rows/block. Warp w == head w. Lane l: rg = l&7 (rows rg*4..rg*4+3),
// q = l>>3, col group cg = w*4+q (cols 4cg..4cg+3). 4x4 register tile.
// Factorized softmax: p = Pi*Qj or Ri*Sj selected by threshold Ti.
// ---------------------------------------------------------------------------
__global__ void __launch_bounds__(256) attn_kernel(const float* __restrict__ gamma,
                                                   const float* __restrict__ beta,
                                                   int dst, float* __restrict__ dout) {
    int b = blockIdx.y;
    int i0 = blockIdx.x * IT;
    int t = threadIdx.x;

    __shared__ float Pi_s[IT * HH], Ri_s[IT * HH], Ti_s[IT * HH];
    __shared__ float gpart[32][HH];
    __shared__ float gmax[HH];
    __shared__ unsigned int mask_s[IT][MW];
    __shared__ __align__(16) float xs[JT][EE];
    __shared__ __align__(16) float p_s[JT * PJ];
    __shared__ float Qt[JT][HH], St[JT][HH];
    __shared__ float s_s[IT * HH];
    __shared__ float lnred[8][8][4][2];
    __shared__ float mu_s[IT], rstd_s[IT];

    const float* xWb = g_xW + (size_t)b * NN * EE;
    const float* ejb = g_ej + (size_t)b * NN * HH;

    {
        int g = t >> 3, hh = t & 7;
        float mx = -INFINITY;
        for (int j = g; j < NN; j += 32) mx = fmaxf(mx, ejb[j * HH + hh]);
        gpart[g][hh] = mx;
    }
    {
        #pragma unroll
        for (int k = 0; k < 2; k++) {
            int idx = t + 256 * k;
            int ii = idx >> 4, w2 = idx & 15;
            int i = i0 + ii;
            mask_s[ii][w2] = (i < NN) ? g_adjbits[(b * NN + i) * MW + w2] : 0u;
        }
    }
    __syncthreads();
    if (t < HH) {
        float mx = gpart[0][t];
        #pragma unroll
        for (int g = 1; g < 32; g++) mx = fmaxf(mx, gpart[g][t]);
        gmax[t] = mx;
    }
    __syncthreads();
    {
        int i = i0 + (t >> 3);
        float ei = (i < NN) ? g_ei[(b * NN + i) * HH + (t & 7)] : 0.f;
        float w = ei + gmax[t & 7];
        float m = fmaxf(w, LEAKY * w);
        Pi_s[t] = fast_exp(ei - m);
        Ri_s[t] = fast_exp(0.2f * ei - m);
        Ti_s[t] = fast_exp(-m);
    }
    __syncthreads();

    int w = t >> 5;
    int l = t & 31;
    int rg = l & 7;
    int q = l >> 3;
    int cg = w * 4 + q;
    bool sowner = (q == 0);
    int ii_t = t >> 3;
    int jj_t = t & 7;

    float Pi_r[HH], Ri_r[HH], Ti_r[HH];
    #pragma unroll
    for (int hh = 0; hh < HH; hh++) {
        Pi_r[hh] = Pi_s[ii_t * HH + hh];
        Ri_r[hh] = Ri_s[ii_t * HH + hh];
        Ti_r[hh] = Ti_s[ii_t * HH + hh];
    }

    float4 acc[4];
    float sacc[4];
    #pragma unroll
    for (int r = 0; r < 4; r++) { acc[r] = make_float4(0.f, 0.f, 0.f, 0.f); sacc[r] = 0.f; }

    for (int j0 = 0; j0 < NN; j0 += JT) {
        {
            float4* d4 = (float4*)&xs[0][0];
            #pragma unroll
            for (int k = 0; k < 2; k++) {
                int idx = t + 256 * k;
                int jj = idx >> 5;
                int j = j0 + jj;
                d4[idx] = (j < NN) ? ((const float4*)(xWb + (size_t)j * EE))[idx & 31]
                                   : make_float4(0.f, 0.f, 0.f, 0.f);
            }
        }
        if (t < JT * HH) {
            int jj = t >> 3, hh = t & 7;
            int j = j0 + jj;
            float e = (j < NN) ? ejb[j * HH + hh] : 0.f;
            Qt[jj][hh] = fast_exp(e);
            St[jj][hh] = fast_exp(0.2f * e);
        }
        __syncthreads();

        #pragma unroll
        for (int k = 0; k < 2; k++) {
            int jj = jj_t + 8 * k;
            int j = j0 + jj;
            float* pd = &p_s[jj * PJ + ii_t];
            if (j < NN && ((mask_s[ii_t][j >> 5] >> (j & 31)) & 1u)) {
                float4 q0 = *(const float4*)&Qt[jj][0];
                float4 q1 = *(const float4*)&Qt[jj][4];
                float4 sp0 = *(const float4*)&St[jj][0];
                float4 sp1 = *(const float4*)&St[jj][4];
                pd[0 * PH] = fsel_ge(Pi_r[0] * q0.x, Ri_r[0] * sp0.x, Ti_r[0]);
                pd[1 * PH] = fsel_ge(Pi_r[1] * q0.y, Ri_r[1] * sp0.y, Ti_r[1]);
                pd[2 * PH] = fsel_ge(Pi_r[2] * q0.z, Ri_r[2] * sp0.z, Ti_r[2]);
                pd[3 * PH] = fsel_ge(Pi_r[3] * q0.w, Ri_r[3] * sp0.w, Ti_r[3]);
                pd[4 * PH] = fsel_ge(Pi_r[4] * q1.x, Ri_r[4] * sp1.x, Ti_r[4]);
                pd[5 * PH] = fsel_ge(Pi_r[5] * q1.y, Ri_r[5] * sp1.y, Ti_r[5]);
                pd[6 * PH] = fsel_ge(Pi_r[6] * q1.z, Ri_r[6] * sp1.z, Ti_r[6]);
                pd[7 * PH] = fsel_ge(Pi_r[7] * q1.w, Ri_r[7] * sp1.w, Ti_r[7]);
            } else {
                #pragma unroll
                for (int hh = 0; hh < HH; hh++) pd[hh * PH] = 0.f;
            }
        }
        __syncthreads();

        #pragma unroll 4
        for (int jj = 0; jj < JT; jj++) {
            float4 p4 = *(const float4*)&p_s[jj * PJ + w * PH + rg * 4];
            float4 xv = *(const float4*)&xs[jj][4 * cg];
            acc[0].x = fmaf(p4.x, xv.x, acc[0].x);
            acc[0].y = fmaf(p4.x, xv.y, acc[0].y);
            acc[0].z = fmaf(p4.x, xv.z, acc[0].z);
            acc[0].w = fmaf(p4.x, xv.w, acc[0].w);
            acc[1].x = fmaf(p4.y, xv.x, acc[1].x);
            acc[1].y = fmaf(p4.y, xv.y, acc[1].y);
            acc[1].z = fmaf(p4.y, xv.z, acc[1].z);
            acc[1].w = fmaf(p4.y, xv.w, acc[1].w);
            acc[2].x = fmaf(p4.z, xv.x, acc[2].x);
            acc[2].y = fmaf(p4.z, xv.y, acc[2].y);
            acc[2].z = fmaf(p4.z, xv.z, acc[2].z);
            acc[2].w = fmaf(p4.z, xv.w, acc[2].w);
            acc[3].x = fmaf(p4.w, xv.x, acc[3].x);
            acc[3].y = fmaf(p4.w, xv.y, acc[3].y);
            acc[3].z = fmaf(p4.w, xv.z, acc[3].z);
            acc[3].w = fmaf(p4.w, xv.w, acc[3].w);
            if (sowner) {
                sacc[0] += p4.x; sacc[1] += p4.y;
                sacc[2] += p4.z; sacc[3] += p4.w;
            }
        }
        __syncthreads();
    }

    if (sowner) {
        #pragma unroll
        for (int r = 0; r < 4; r++) s_s[(rg * 4 + r) * HH + w] = sacc[r];
    }
    __syncthreads();

    float4 val[4];
    #pragma unroll
    for (int r = 0; r < 4; r++) {
        int ii = rg * 4 + r;
        int i = i0 + ii;
        float sv = s_s[ii * HH + w];
        float4 xwv = (i < NN) ? *(const float4*)(xWb + (size_t)i * EE + 4 * cg)
                              : make_float4(0.f, 0.f, 0.f, 0.f);
        float inv = 1.f / sv;
        val[r].x = acc[r].x * inv + xwv.x;
        val[r].y = acc[r].y * inv + xwv.y;
        val[r].z = acc[r].z * inv + xwv.z;
        val[r].w = acc[r].w * inv + xwv.w;
        float s1 = val[r].x + val[r].y + val[r].z + val[r].w;
        float s2 = val[r].x * val[r].x + val[r].y * val[r].y +
                   val[r].z * val[r].z + val[r].w * val[r].w;
        s1 += __shfl_xor_sync(0xffffffffu, s1, 8);
        s2 += __shfl_xor_sync(0xffffffffu, s2, 8);
        s1 += __shfl_xor_sync(0xffffffffu, s1, 16);
        s2 += __shfl_xor_sync(0xffffffffu, s2, 16);
        if (sowner) { lnred[w][rg][r][0] = s1; lnred[w][rg][r][1] = s2; }
    }
    __syncthreads();
    if (t < IT) {
        int rg2 = t >> 2, r2 = t & 3;
        float a = 0.f, qq = 0.f;
        #pragma unroll
        for (int w2 = 0; w2 < 8; w2++) {
            a += lnred[w2][rg2][r2][0];
            qq += lnred[w2][rg2][r2][1];
        }
        float mu = a * (1.f / EE);
        float var = qq * (1.f / EE) - mu * mu;
        mu_s[t] = mu;
        rstd_s[t] = rsqrtf(var + LN_EPS);
    }
    __syncthreads();

    float* o = (dst < 0) ? dout : &g_x[dst][0];
    float4 gv = *(const float4*)&gamma[4 * cg];
    float4 bv = *(const float4*)&beta[4 * cg];
    #pragma unroll
    for (int r = 0; r < 4; r++) {
        int ii = rg * 4 + r;
        int i = i0 + ii;
        if (i >= NN) continue;
        float mu = mu_s[ii], rstd = rstd_s[ii];
        float y0 = (val[r].x - mu) * rstd * gv.x + bv.x;
        float y1 = (val[r].y - mu) * rstd * gv.y + bv.y;
        float y2 = (val[r].z - mu) * rstd * gv.z + bv.z;
        float y3 = (val[r].w - mu) * rstd * gv.w + bv.w;
        y0 = y0 > 0.f ? y0 : (fast_exp(y0) - 1.f);
        y1 = y1 > 0.f ? y1 : (fast_exp(y1) - 1.f);
        y2 = y2 > 0.f ? y2 : (fast_exp(y2) - 1.f);
        y3 = y3 > 0.f ? y3 : (fast_exp(y3) - 1.f);
        *(float4*)(o + ((size_t)(b * NN + i)) * EE + 4 * cg) =
            make_float4(y0, y1, y2, y3);
    }
}

// ---------------------------------------------------------------------------
extern "C" void kernel_launch(void* const* d_in, const int* in_sizes, int n_in,
                              void* d_out, int out_size) {
    const float* depot_xy = (const float*)d_in[0];
    const float* node5    = (const float*)d_in[1];
    const void*  adj_raw  = (const void*)d_in[2];
    const float* depW  = (const float*)d_in[3];
    const float* depb  = (const float*)d_in[4];
    const float* nodeW = (const float*)d_in[5];
    const float* nodeb = (const float*)d_in[6];
    const float* W     = (const float*)d_in[7];
    const float* attn  = (const float*)d_in[8];
    const float* ln_g  = (const float*)d_in[9];
    const float* ln_b  = (const float*)d_in[10];
    float* out = (float*)d_out;

    cudaFuncSetAttribute(xw_kernel,
                         cudaFuncAttributeMaxDynamicSharedMemorySize, XW_SMEM);

    probe_mask_kernel<<<1, 256>>>((const unsigned int*)adj_raw);
    convert_bits_kernel<<<BB * NN, 512>>>(adj_raw);

    embed_kernel<<<BB * NN, EE>>>(depot_xy, node5, depW, depb, nodeW, nodeb);

    dim3 agrid((NN + IT - 1) / IT, BB);
    int cur = 0;
    for (int l = 0; l < LL; l++) {
        xw_kernel<<<XWGRID, 256, XW_SMEM>>>(cur,
                                            W + (size_t)l * EE * EE,
                                            attn + (size_t)l * HH * 2 * HD);
        int dst = (l == LL - 1) ? -1 : (1 - cur);
        attn_kernel<<<agrid, 256>>>(ln_g + (size_t)l * EE,
                                    ln_b + (size_t)l * EE,
                                    dst, out);
        cur = 1 - cur;
    }
}

// round 15
// speedup vs baseline: 1.3991x; 1.0393x over previous
#include <cuda_runtime.h>
#include <math.h>

#define BB 16
#define PP 500
#define NN 501
#define EE 128
#define HH 8
#define HD 16
#define LL 3
#define LEAKY 0.2f
#define LN_EPS 1e-5f
#define IT 32
#define JT 16
#define MW 16    // mask words per row (501 bits -> 16 u32)
#define PH 36    // p head stride (floats)
#define PJ 292   // p jj stride (floats) = 8*36+4
#define NROWS (BB * NN)          // 8016
#define XWROWS 32
#define XWGRID ((NROWS + XWROWS - 1) / XWROWS)   // 251
#define XW_SMEM ((EE * EE + XWROWS * EE) * 4)    // 80 KB
#define NQ (NN * HH)             // 4008
// attn dynamic smem layout (floats)
#define AOFF_QS 0
#define AOFF_SS NQ
#define AOFF_XS (2 * NQ)
#define AOFF_P  (2 * NQ + JT * EE)
#define ATTN_SMEM ((2 * NQ + JT * EE + JT * PJ) * 4)   // 58944 B

// Scratch (device globals; no runtime allocation)
__device__ float g_x[2][(size_t)BB * NN * EE];
__device__ float g_xW[(size_t)BB * NN * EE];
__device__ float g_ei[BB * NN * HH];
__device__ float g_ej[BB * NN * HH];
__device__ unsigned int g_adjbits[BB * NN * MW];
__device__ int g_mask_kind;

// FFMA-only exp, rel err ~2e-7, no MUFU.
__device__ __forceinline__ float fast_exp(float x) {
    x = fmaxf(x, -80.f);
    float y = x * 1.4426950408889634f;
    float t = y + 12582912.f;
    int n = __float_as_int(t) - 0x4B400000;
    float f = y - (t - 12582912.f);
    float u = f * 0.6931471805599453f;
    float r = fmaf(u, 1.38888889e-3f, 8.33333333e-3f);
    r = fmaf(r, u, 4.16666667e-2f);
    r = fmaf(r, u, 1.66666667e-1f);
    r = fmaf(r, u, 0.5f);
    r = fmaf(r, u, 1.0f);
    r = fmaf(r, u, 1.0f);
    return r * __int_as_float((n + 127) << 23);
}
__device__ __forceinline__ float fsel_ge(float a, float b, float thr) {
    return (a >= thr) ? a : b;
}

// ---------------------------------------------------------------------------
__global__ void probe_mask_kernel(const unsigned int* __restrict__ w) {
    __shared__ int s_u8, s_f32;
    if (threadIdx.x == 0) { s_u8 = 0; s_f32 = 0; }
    __syncthreads();
    for (int idx = threadIdx.x; idx < 4096; idx += blockDim.x) {
        unsigned int v = w[idx];
        if (v == 0x3f800000u) atomicOr(&s_f32, 1);
        else if (v > 1u)      atomicOr(&s_u8, 1);
    }
    __syncthreads();
    if (threadIdx.x == 0) g_mask_kind = s_f32 ? 2 : (s_u8 ? 1 : 0);
}

__global__ void convert_bits_kernel(const void* __restrict__ adj_raw) {
    int bn = blockIdx.x;
    int t = threadIdx.x;
    int kind = g_mask_kind;
    bool v = false;
    if (t < NN) {
        size_t idx = (size_t)bn * NN + t;
        if (kind == 1)      v = ((const unsigned char*)adj_raw)[idx] != 0;
        else if (kind == 2) v = ((const float*)adj_raw)[idx] != 0.0f;
        else                v = ((const int*)adj_raw)[idx] != 0;
    }
    unsigned int word = __ballot_sync(0xffffffffu, v);
    if ((t & 31) == 0) g_adjbits[bn * MW + (t >> 5)] = word;
}

// ---------------------------------------------------------------------------
__global__ void embed_kernel(const float* __restrict__ depot_xy,
                             const float* __restrict__ node5,
                             const float* __restrict__ depW,
                             const float* __restrict__ depb,
                             const float* __restrict__ nodeW,
                             const float* __restrict__ nodeb) {
    int bn = blockIdx.x;
    int b = bn / NN, n = bn % NN;
    int e = threadIdx.x;
    float v;
    if (n == 0) {
        float x0 = depot_xy[b * 2 + 0];
        float x1 = depot_xy[b * 2 + 1];
        v = fmaf(x0, depW[0 * EE + e], fmaf(x1, depW[1 * EE + e], depb[e]));
    } else {
        int p = n - 1;
        const float* f = node5 + ((size_t)b * PP + p) * 5;
        v = nodeb[e];
        #pragma unroll
        for (int k = 0; k < 5; k++) v = fmaf(f[k], nodeW[k * EE + e], v);
    }
    g_x[0][(size_t)bn * EE + e] = v;
}

// ---------------------------------------------------------------------------
// xW = x @ W[l] + fused ei/ej. grid = 251, block = 256, 32 rows/block.
// ---------------------------------------------------------------------------
__global__ void __launch_bounds__(256) xw_kernel(int src,
                                                const float* __restrict__ Wl,
                                                const float* __restrict__ attn_l) {
    extern __shared__ float sm[];
    float* ws = sm;                 // [k][e], 128*128
    float* xs = sm + EE * EE;       // [r][k], 32*128
    int t = threadIdx.x;
    int row0 = blockIdx.x * XWROWS;

    {
        const float4* W4 = (const float4*)Wl;
        float4* ws4 = (float4*)ws;
        #pragma unroll
        for (int k = 0; k < 16; k++) ws4[t + 256 * k] = W4[t + 256 * k];
        const float4* x4 = (const float4*)(&g_x[src][0] + (size_t)row0 * EE);
        float4* xs4 = (float4*)xs;
        int maxf4 = (NROWS - row0) * (EE / 4);
        #pragma unroll
        for (int k = 0; k < 4; k++) {
            int idx = t + 256 * k;
            xs4[idx] = (idx < maxf4) ? x4[idx] : make_float4(0.f, 0.f, 0.f, 0.f);
        }
    }
    __syncthreads();

    int c4 = t & 31;
    int rg = t >> 5;

    float4 acc[4];
    #pragma unroll
    for (int r = 0; r < 4; r++) acc[r] = make_float4(0.f, 0.f, 0.f, 0.f);

    #pragma unroll 8
    for (int k = 0; k < EE; k += 4) {
        float4 w0 = *(const float4*)&ws[(k + 0) * EE + 4 * c4];
        float4 w1 = *(const float4*)&ws[(k + 1) * EE + 4 * c4];
        float4 w2 = *(const float4*)&ws[(k + 2) * EE + 4 * c4];
        float4 w3 = *(const float4*)&ws[(k + 3) * EE + 4 * c4];
        #pragma unroll
        for (int r = 0; r < 4; r++) {
            float4 xv = *(const float4*)&xs[(rg * 4 + r) * EE + k];
            acc[r].x = fmaf(xv.x, w0.x, acc[r].x);
            acc[r].y = fmaf(xv.x, w0.y, acc[r].y);
            acc[r].z = fmaf(xv.x, w0.z, acc[r].z);
            acc[r].w = fmaf(xv.x, w0.w, acc[r].w);
            acc[r].x = fmaf(xv.y, w1.x, acc[r].x);
            acc[r].y = fmaf(xv.y, w1.y, acc[r].y);
            acc[r].z = fmaf(xv.y, w1.z, acc[r].z);
            acc[r].w = fmaf(xv.y, w1.w, acc[r].w);
            acc[r].x = fmaf(xv.z, w2.x, acc[r].x);
            acc[r].y = fmaf(xv.z, w2.y, acc[r].y);
            acc[r].z = fmaf(xv.z, w2.z, acc[r].z);
            acc[r].w = fmaf(xv.z, w2.w, acc[r].w);
            acc[r].x = fmaf(xv.w, w3.x, acc[r].x);
            acc[r].y = fmaf(xv.w, w3.y, acc[r].y);
            acc[r].z = fmaf(xv.w, w3.z, acc[r].z);
            acc[r].w = fmaf(xv.w, w3.w, acc[r].w);
        }
    }

    int h = c4 >> 2;
    int dq = (c4 & 3) * 4;
    float4 a1 = *(const float4*)&attn_l[h * 2 * HD + dq];
    float4 a2 = *(const float4*)&attn_l[h * 2 * HD + HD + dq];
    #pragma unroll
    for (int r = 0; r < 4; r++) {
        int row = row0 + rg * 4 + r;
        if (row >= NROWS) break;
        *(float4*)(g_xW + (size_t)row * EE + 4 * c4) = acc[r];
        float vi = acc[r].x * a1.x + acc[r].y * a1.y + acc[r].z * a1.z + acc[r].w * a1.w;
        float vj = acc[r].x * a2.x + acc[r].y * a2.y + acc[r].z * a2.z + acc[r].w * a2.w;
        vi += __shfl_xor_sync(0xffffffffu, vi, 1);
        vj += __shfl_xor_sync(0xffffffffu, vj, 1);
        vi += __shfl_xor_sync(0xffffffffu, vi, 2);
        vj += __shfl_xor_sync(0xffffffffu, vj, 2);
        if ((c4 & 3) == 0) {
            g_ei[row * HH + h] = vi;
            g_ej[row * HH + h] = vj;
        }
    }
}

// ---------------------------------------------------------------------------
// Attention + residual + LayerNorm + ELU. grid = (16, B), block = 256.
// Per-block Q/S exp tables (dynamic smem) -> fused stage+p phase, 2 syncs/tile.
// Warp w == head w; lane: rg = l&7 (rows rg*4..+3), q = l>>3, cg = w*4+q.
// ---------------------------------------------------------------------------
__global__ void __launch_bounds__(256) attn_kernel(const float* __restrict__ gamma,
                                                   const float* __restrict__ beta,
                                                   int dst, float* __restrict__ dout) {
    int b = blockIdx.y;
    int i0 = blockIdx.x * IT;
    int t = threadIdx.x;

    extern __shared__ float dyn[];
    float* Qs  = dyn + AOFF_QS;
    float* Ss  = dyn + AOFF_SS;
    float* xs  = dyn + AOFF_XS;   // [jj][e]
    float* p_s = dyn + AOFF_P;    // [jj*PJ + h*PH + ii]

    __shared__ float Pi_s[IT * HH], Ri_s[IT * HH], Ti_s[IT * HH];
    __shared__ float gpart[32][HH];
    __shared__ float gmax[HH];
    __shared__ unsigned int mask_s[IT][MW];
    __shared__ float lnred[8][8][4][2];
    __shared__ float mu_s[IT], rstd_s[IT];

    const float* xWb = g_xW + (size_t)b * NN * EE;
    const float* ejb = g_ej + (size_t)b * NN * HH;

    // prologue phase 1: gpart, mask, exp tables
    {
        int g = t >> 3, hh = t & 7;
        float mx = -INFINITY;
        for (int j = g; j < NN; j += 32) mx = fmaxf(mx, ejb[j * HH + hh]);
        gpart[g][hh] = mx;
    }
    {
        #pragma unroll
        for (int k = 0; k < 2; k++) {
            int idx = t + 256 * k;
            int ii = idx >> 4, w2 = idx & 15;
            int i = i0 + ii;
            mask_s[ii][w2] = (i < NN) ? g_adjbits[(b * NN + i) * MW + w2] : 0u;
        }
    }
    for (int idx = t; idx < NQ; idx += 256) {
        float e = ejb[idx];
        Qs[idx] = fast_exp(e);
        Ss[idx] = fast_exp(0.2f * e);
    }
    __syncthreads();
    if (t < HH) {
        float mx = gpart[0][t];
        #pragma unroll
        for (int g = 1; g < 32; g++) mx = fmaxf(mx, gpart[g][t]);
        gmax[t] = mx;
    }
    __syncthreads();
    {
        int i = i0 + (t >> 3);
        float ei = (i < NN) ? g_ei[(b * NN + i) * HH + (t & 7)] : 0.f;
        float w = ei + gmax[t & 7];
        float m = fmaxf(w, LEAKY * w);
        Pi_s[t] = fast_exp(ei - m);
        Ri_s[t] = fast_exp(0.2f * ei - m);
        Ti_s[t] = fast_exp(-m);
    }
    __syncthreads();

    int w = t >> 5;
    int l = t & 31;
    int rg = l & 7;
    int q = l >> 3;
    int cg = w * 4 + q;
    bool sowner = (q == 0);
    int ii_t = t >> 3;
    int jj_t = t & 7;

    float Pi_r[HH], Ri_r[HH], Ti_r[HH];
    #pragma unroll
    for (int hh = 0; hh < HH; hh++) {
        Pi_r[hh] = Pi_s[ii_t * HH + hh];
        Ri_r[hh] = Ri_s[ii_t * HH + hh];
        Ti_r[hh] = Ti_s[ii_t * HH + hh];
    }

    float4 acc[4];
    float sacc[4];
    #pragma unroll
    for (int r = 0; r < 4; r++) { acc[r] = make_float4(0.f, 0.f, 0.f, 0.f); sacc[r] = 0.f; }

    for (int j0 = 0; j0 < NN; j0 += JT) {
        // fused phase: stage xs + compute p (tables are ready)
        {
            float4* d4 = (float4*)xs;
            #pragma unroll
            for (int k = 0; k < 2; k++) {
                int idx = t + 256 * k;
                int jj = idx >> 5;
                int j = j0 + jj;
                d4[idx] = (j < NN) ? ((const float4*)(xWb + (size_t)j * EE))[idx & 31]
                                   : make_float4(0.f, 0.f, 0.f, 0.f);
            }
        }
        #pragma unroll
        for (int k = 0; k < 2; k++) {
            int jj = jj_t + 8 * k;
            int j = j0 + jj;
            float* pd = &p_s[jj * PJ + ii_t];
            if (j < NN && ((mask_s[ii_t][j >> 5] >> (j & 31)) & 1u)) {
                float4 q0 = *(const float4*)&Qs[j * 8];
                float4 q1 = *(const float4*)&Qs[j * 8 + 4];
                float4 sp0 = *(const float4*)&Ss[j * 8];
                float4 sp1 = *(const float4*)&Ss[j * 8 + 4];
                pd[0 * PH] = fsel_ge(Pi_r[0] * q0.x, Ri_r[0] * sp0.x, Ti_r[0]);
                pd[1 * PH] = fsel_ge(Pi_r[1] * q0.y, Ri_r[1] * sp0.y, Ti_r[1]);
                pd[2 * PH] = fsel_ge(Pi_r[2] * q0.z, Ri_r[2] * sp0.z, Ti_r[2]);
                pd[3 * PH] = fsel_ge(Pi_r[3] * q0.w, Ri_r[3] * sp0.w, Ti_r[3]);
                pd[4 * PH] = fsel_ge(Pi_r[4] * q1.x, Ri_r[4] * sp1.x, Ti_r[4]);
                pd[5 * PH] = fsel_ge(Pi_r[5] * q1.y, Ri_r[5] * sp1.y, Ti_r[5]);
                pd[6 * PH] = fsel_ge(Pi_r[6] * q1.z, Ri_r[6] * sp1.z, Ti_r[6]);
                pd[7 * PH] = fsel_ge(Pi_r[7] * q1.w, Ri_r[7] * sp1.w, Ti_r[7]);
            } else {
                #pragma unroll
                for (int hh = 0; hh < HH; hh++) pd[hh * PH] = 0.f;
            }
        }
        __syncthreads();

        #pragma unroll 4
        for (int jj = 0; jj < JT; jj++) {
            float4 p4 = *(const float4*)&p_s[jj * PJ + w * PH + rg * 4];
            float4 xv = *(const float4*)&xs[jj * EE + 4 * cg];
            acc[0].x = fmaf(p4.x, xv.x, acc[0].x);
            acc[0].y = fmaf(p4.x, xv.y, acc[0].y);
            acc[0].z = fmaf(p4.x, xv.z, acc[0].z);
            acc[0].w = fmaf(p4.x, xv.w, acc[0].w);
            acc[1].x = fmaf(p4.y, xv.x, acc[1].x);
            acc[1].y = fmaf(p4.y, xv.y, acc[1].y);
            acc[1].z = fmaf(p4.y, xv.z, acc[1].z);
            acc[1].w = fmaf(p4.y, xv.w, acc[1].w);
            acc[2].x = fmaf(p4.z, xv.x, acc[2].x);
            acc[2].y = fmaf(p4.z, xv.y, acc[2].y);
            acc[2].z = fmaf(p4.z, xv.z, acc[2].z);
            acc[2].w = fmaf(p4.z, xv.w, acc[2].w);
            acc[3].x = fmaf(p4.w, xv.x, acc[3].x);
            acc[3].y = fmaf(p4.w, xv.y, acc[3].y);
            acc[3].z = fmaf(p4.w, xv.z, acc[3].z);
            acc[3].w = fmaf(p4.w, xv.w, acc[3].w);
            if (sowner) {
                sacc[0] += p4.x; sacc[1] += p4.y;
                sacc[2] += p4.z; sacc[3] += p4.w;
            }
        }
        __syncthreads();
    }

    // epilogue: row sums via shuffle (lane rg holds rows rg*4..rg*4+3)
    float4 val[4];
    #pragma unroll
    for (int r = 0; r < 4; r++) {
        float sv = __shfl_sync(0xffffffffu, sacc[r], rg);
        int ii = rg * 4 + r;
        int i = i0 + ii;
        float4 xwv = (i < NN) ? *(const float4*)(xWb + (size_t)i * EE + 4 * cg)
                              : make_float4(0.f, 0.f, 0.f, 0.f);
        float inv = 1.f / sv;
        val[r].x = acc[r].x * inv + xwv.x;
        val[r].y = acc[r].y * inv + xwv.y;
        val[r].z = acc[r].z * inv + xwv.z;
        val[r].w = acc[r].w * inv + xwv.w;
        float s1 = val[r].x + val[r].y + val[r].z + val[r].w;
        float s2 = val[r].x * val[r].x + val[r].y * val[r].y +
                   val[r].z * val[r].z + val[r].w * val[r].w;
        s1 += __shfl_xor_sync(0xffffffffu, s1, 8);
        s2 += __shfl_xor_sync(0xffffffffu, s2, 8);
        s1 += __shfl_xor_sync(0xffffffffu, s1, 16);
        s2 += __shfl_xor_sync(0xffffffffu, s2, 16);
        if (sowner) { lnred[w][rg][r][0] = s1; lnred[w][rg][r][1] = s2; }
    }
    __syncthreads();
    if (t < IT) {
        int rg2 = t >> 2, r2 = t & 3;
        float a = 0.f, qq = 0.f;
        #pragma unroll
        for (int w2 = 0; w2 < 8; w2++) {
            a += lnred[w2][rg2][r2][0];
            qq += lnred[w2][rg2][r2][1];
        }
        float mu = a * (1.f / EE);
        float var = qq * (1.f / EE) - mu * mu;
        mu_s[t] = mu;
        rstd_s[t] = rsqrtf(var + LN_EPS);
    }
    __syncthreads();

    float* o = (dst < 0) ? dout : &g_x[dst][0];
    float4 gv = *(const float4*)&gamma[4 * cg];
    float4 bv = *(const float4*)&beta[4 * cg];
    #pragma unroll
    for (int r = 0; r < 4; r++) {
        int ii = rg * 4 + r;
        int i = i0 + ii;
        if (i >= NN) continue;
        float mu = mu_s[ii], rstd = rstd_s[ii];
        float y0 = (val[r].x - mu) * rstd * gv.x + bv.x;
        float y1 = (val[r].y - mu) * rstd * gv.y + bv.y;
        float y2 = (val[r].z - mu) * rstd * gv.z + bv.z;
        float y3 = (val[r].w - mu) * rstd * gv.w + bv.w;
        y0 = y0 > 0.f ? y0 : (fast_exp(y0) - 1.f);
        y1 = y1 > 0.f ? y1 : (fast_exp(y1) - 1.f);
        y2 = y2 > 0.f ? y2 : (fast_exp(y2) - 1.f);
        y3 = y3 > 0.f ? y3 : (fast_exp(y3) - 1.f);
        *(float4*)(o + ((size_t)(b * NN + i)) * EE + 4 * cg) =
            make_float4(y0, y1, y2, y3);
    }
}

// ---------------------------------------------------------------------------
extern "C" void kernel_launch(void* const* d_in, const int* in_sizes, int n_in,
                              void* d_out, int out_size) {
    const float* depot_xy = (const float*)d_in[0];
    const float* node5    = (const float*)d_in[1];
    const void*  adj_raw  = (const void*)d_in[2];
    const float* depW  = (const float*)d_in[3];
    const float* depb  = (const float*)d_in[4];
    const float* nodeW = (const float*)d_in[5];
    const float* nodeb = (const float*)d_in[6];
    const float* W     = (const float*)d_in[7];
    const float* attn  = (const float*)d_in[8];
    const float* ln_g  = (const float*)d_in[9];
    const float* ln_b  = (const float*)d_in[10];
    float* out = (float*)d_out;

    cudaFuncSetAttribute(xw_kernel,
                         cudaFuncAttributeMaxDynamicSharedMemorySize, XW_SMEM);
    cudaFuncSetAttribute(attn_kernel,
                         cudaFuncAttributeMaxDynamicSharedMemorySize, ATTN_SMEM);

    probe_mask_kernel<<<1, 256>>>((const unsigned int*)adj_raw);
    convert_bits_kernel<<<BB * NN, 512>>>(adj_raw);

    embed_kernel<<<BB * NN, EE>>>(depot_xy, node5, depW, depb, nodeW, nodeb);

    dim3 agrid((NN + IT - 1) / IT, BB);
    int cur = 0;
    for (int l = 0; l < LL; l++) {
        xw_kernel<<<XWGRID, 256, XW_SMEM>>>(cur,
                                            W + (size_t)l * EE * EE,
                                            attn + (size_t)l * HH * 2 * HD);
        int dst = (l == LL - 1) ? -1 : (1 - cur);
        attn_kernel<<<agrid, 256, ATTN_SMEM>>>(ln_g + (size_t)l * EE,
                                               ln_b + (size_t)l * EE,
                                               dst, out);
        cur = 1 - cur;
    }
}